// round 1
// baseline (speedup 1.0000x reference)
#include <cuda_runtime.h>

// gdfn_region_batch: fused single-kernel implementation.
// B=8, C=3, H=W=512, KS=3.
//
// Per 32x32 output tile (one CTA):
//   A) stage img_p = pad(img)+noise over tile+3 halo into SMEM (+ raw img tile)
//   B) stage1: per-pixel (tile+2 halo) per-channel mean/std(ddof=1) over 3x3
//      window, w=exp(-d^2/(2var)), img_3d = min_c w (9 floats), img_r=num/den
//   C) stage2: argmin/argmax over 3x3 window of img_r (zero-padded), select
//      img_3d[id] -> img_3d_mod (tile+1 halo)
//   D) stage3: img_mod = sum(img_e * m_e)/sum(m_e) with m_e = 3x3 window of
//      img_3d_mod (zero-padded); blend with re_mask; write out.
// Per-batch sel==false -> plain copy of img (skips all compute).

#define TS 32
#define R2S 36           // tile + 2 halo each side (stage1 region)
#define R1S 34           // tile + 1 halo each side (stage2 region)
#define PS  38           // tile + 3 halo each side (img_p region)

#define IMGP_PITCH 39
#define W_PITCH    37
#define R_PITCH    37
#define MOD_PITCH  35
#define IMG_PITCH  33

#define SMEM_FLOATS (3*PS*IMGP_PITCH + 9*R2S*W_PITCH + R2S*R_PITCH + R1S*MOD_PITCH + 3*TS*IMG_PITCH)
#define SMEM_BYTES  (SMEM_FLOATS * 4)

// sel / mix_sel may arrive as int32 (4B) or bool (1B). For int32 storage the
// pad bytes {1,2,3,5,6,7} are always zero (values are 0/1); for bool storage
// they hold elements 1,2,3,5,6,7. Deterministic per dataset.
__device__ __forceinline__ bool read_flag(const void* p, int b) {
    const unsigned char* u = (const unsigned char*)p;
    unsigned probe = (unsigned)u[1] | u[2] | u[3] | u[5] | u[6] | u[7];
    if (probe == 0u) return ((const int*)p)[b] != 0;   // int32-like
    return u[b] != 0;                                   // bool-like
}

__global__ __launch_bounds__(256, 2)
void gdfn_kernel(const float* __restrict__ img,
                 const float* __restrict__ noise,
                 const float* __restrict__ re_mask,
                 const void*  __restrict__ sel,
                 const void*  __restrict__ mix_sel,
                 float* __restrict__ out)
{
    const int b  = blockIdx.z;
    const int y0 = blockIdx.y * TS;
    const int x0 = blockIdx.x * TS;
    const int tid = threadIdx.x;

    const bool apply = read_flag(sel, b);
    if (!apply) {
        // out = img for this tile (whole-batch copy path)
        for (int t = tid; t < 3 * TS * TS; t += 256) {
            int c = t / (TS * TS); int r = t % (TS * TS);
            int ty = r / TS, tx = r % TS;
            size_t g = (((size_t)(b * 3 + c)) * 512 + (y0 + ty)) * 512 + (x0 + tx);
            out[g] = img[g];
        }
        return;
    }
    const bool mix = read_flag(mix_sel, b);

    extern __shared__ float sm[];
    float* smimgp = sm;                                   // [3][PS][IMGP_PITCH]
    float* smw    = smimgp + 3 * PS * IMGP_PITCH;         // [9][R2S][W_PITCH]
    float* smr    = smw    + 9 * R2S * W_PITCH;           // [R2S][R_PITCH]
    float* smmod  = smr    + R2S * R_PITCH;               // [R1S][MOD_PITCH]
    float* smimg  = smmod  + R1S * MOD_PITCH;             // [3][TS][IMG_PITCH]

    // ---- Phase A: img_p = pad(img)+noise over tile+3 halo; raw img tile ----
    for (int t = tid; t < 3 * PS * PS; t += 256) {
        int c = t / (PS * PS); int r = t % (PS * PS);
        int iy = r / PS, ix = r % PS;
        int gy = y0 - 3 + iy, gx = x0 - 3 + ix;   // unpadded coords; padded = +1
        float v = 0.f;
        if (gy >= -1 && gy <= 512 && gx >= -1 && gx <= 512) {
            v = noise[(((size_t)(b * 3 + c)) * 514 + (gy + 1)) * 514 + (gx + 1)];
            if ((unsigned)gy < 512u && (unsigned)gx < 512u)
                v += img[(((size_t)(b * 3 + c)) * 512 + gy) * 512 + gx];
        }
        smimgp[(c * PS + iy) * IMGP_PITCH + ix] = v;
    }
    for (int t = tid; t < 3 * TS * TS; t += 256) {
        int c = t / (TS * TS); int r = t % (TS * TS);
        int ty = r / TS, tx = r % TS;
        smimg[(c * TS + ty) * IMG_PITCH + tx] =
            img[(((size_t)(b * 3 + c)) * 512 + (y0 + ty)) * 512 + (x0 + tx)];
    }
    __syncthreads();

    // ---- Phase B: stage1 over tile+2 halo ----
    for (int t = tid; t < R2S * R2S; t += 256) {
        int py = t / R2S, px = t % R2S;
        int gy = y0 - 2 + py, gx = x0 - 2 + px;
        float rv = 0.f;  // zero-pad value of img_r for out-of-image positions
        if ((unsigned)gy < 512u && (unsigned)gx < 512u) {
            float vv[3][9];
            float w3[9];
            #pragma unroll
            for (int c = 0; c < 3; c++) {
                float s = 0.f;
                #pragma unroll
                for (int k = 0; k < 9; k++) {
                    float v = smimgp[(c * PS + py + k / 3) * IMGP_PITCH + px + (k % 3)];
                    vv[c][k] = v; s += v;
                }
                float m = s * (1.f / 9.f);
                float s2 = 0.f;
                #pragma unroll
                for (int k = 0; k < 9; k++) { float d = vv[c][k] - m; s2 += d * d; }
                float inv = 4.f / s2;   // 1/(2*var), var = s2/8 (ddof=1)
                #pragma unroll
                for (int k = 0; k < 9; k++) {
                    float d = vv[c][k] - m;
                    float w = __expf(-(d * d) * inv);
                    w3[k] = (c == 0) ? w : fminf(w3[k], w);
                }
            }
            float den = 0.f, num = 0.f;
            #pragma unroll
            for (int k = 0; k < 9; k++) {
                den += w3[k];
                num += (vv[0][k] + vv[1][k] + vv[2][k]) * w3[k];
                smw[(k * R2S + py) * W_PITCH + px] = w3[k];
            }
            rv = num / den;
        }
        smr[py * R_PITCH + px] = rv;
    }
    __syncthreads();

    // ---- Phase C: stage2 over tile+1 halo ----
    for (int t = tid; t < R1S * R1S; t += 256) {
        int qy = t / R1S, qx = t % R1S;
        int gy = y0 - 1 + qy, gx = x0 - 1 + qx;
        float mv = 0.f;  // zero-pad value of img_3d_mod
        if ((unsigned)gy < 512u && (unsigned)gx < 512u) {
            float bmin =  3.4e38f; int amin = 0;
            float bmax = -3.4e38f; int amax = 0;
            #pragma unroll
            for (int k = 0; k < 9; k++) {
                // img_r window: local R2 coords (qy+1-1+ki, qx+1-1+kj) = (qy+ki, qx+kj)
                float v = smr[(qy + k / 3) * R_PITCH + qx + (k % 3)];
                if (v < bmin) { bmin = v; amin = k; }   // first-occurrence, matches jnp.argmin
                if (v > bmax) { bmax = v; amax = k; }   // first-occurrence, matches jnp.argmax
            }
            int id = mix ? amax : amin;
            mv = smw[(id * R2S + (qy + 1)) * W_PITCH + (qx + 1)];
        }
        smmod[qy * MOD_PITCH + qx] = mv;
    }
    __syncthreads();

    // ---- Phase D: stage3 + blend + write ----
    for (int t = tid; t < TS * TS; t += 256) {
        int ty = t / TS, tx = t % TS;
        float m[9]; float den = 0.f;
        #pragma unroll
        for (int k = 0; k < 9; k++) {
            m[k] = smmod[(ty + k / 3) * MOD_PITCH + tx + (k % 3)];
            den += m[k];
        }
        float invden = 1.f / den;
        size_t base = (((size_t)(b * 3)) * 512 + (y0 + ty)) * 512 + (x0 + tx);
        #pragma unroll
        for (int c = 0; c < 3; c++) {
            float num = 0.f;
            #pragma unroll
            for (int k = 0; k < 9; k++)
                num += smimgp[(c * PS + ty + 2 + k / 3) * IMGP_PITCH + tx + 2 + (k % 3)] * m[k];
            float imod = num * invden;
            size_t g = base + (size_t)c * 512 * 512;
            float re = re_mask[g];
            float iv = smimg[(c * TS + ty) * IMG_PITCH + tx];
            out[g] = imod * (1.f - re) + iv * re;
        }
    }
}

extern "C" void kernel_launch(void* const* d_in, const int* in_sizes, int n_in,
                              void* d_out, int out_size) {
    const float* img     = (const float*)d_in[0];
    const float* noise   = (const float*)d_in[1];
    const float* re_mask = (const float*)d_in[2];
    const void*  sel     = d_in[3];
    const void*  mix_sel = d_in[4];
    float* out = (float*)d_out;

    cudaFuncSetAttribute(gdfn_kernel, cudaFuncAttributeMaxDynamicSharedMemorySize, SMEM_BYTES);
    dim3 grid(512 / TS, 512 / TS, 8);
    gdfn_kernel<<<grid, 256, SMEM_BYTES>>>(img, noise, re_mask, sel, mix_sel, out);
}

// round 2
// speedup vs baseline: 1.3206x; 1.3206x over previous
#include <cuda_runtime.h>

// gdfn_region_batch: fused single-kernel implementation, round 2.
// Key changes vs round 1:
//  - min_c exp(-t_c) == exp(-max_c t_c): 27 -> 9 MUFU exps per stage-1 pixel.
//  - dropped smimg tile; phase D reloads img from global (L2-resident).
//  - SMEM 86KB -> ~74KB  => 3 CTAs/SM (launch_bounds(256,3)).
//  - fast divides via __fdividef.

#define TS 32
#define R2S 36           // tile + 2 halo each side (stage1 region)
#define R1S 34           // tile + 1 halo each side (stage2 region)
#define PS  38           // tile + 3 halo each side (img_p region)

#define IMGP_PITCH 39
#define W_PITCH    37
#define R_PITCH    37
#define MOD_PITCH  35

#define SMEM_FLOATS (3*PS*IMGP_PITCH + 9*R2S*W_PITCH + R2S*R_PITCH + R1S*MOD_PITCH)
#define SMEM_BYTES  (SMEM_FLOATS * 4)

// sel / mix_sel may arrive as int32 (4B) or bool (1B). For int32 storage the
// pad bytes {1,2,3,5,6,7} are always zero (values are 0/1); for bool storage
// they hold elements 1,2,3,5,6,7. Deterministic per dataset.
__device__ __forceinline__ bool read_flag(const void* p, int b) {
    const unsigned char* u = (const unsigned char*)p;
    unsigned probe = (unsigned)u[1] | u[2] | u[3] | u[5] | u[6] | u[7];
    if (probe == 0u) return ((const int*)p)[b] != 0;   // int32-like
    return u[b] != 0;                                   // bool-like
}

__global__ __launch_bounds__(256, 3)
void gdfn_kernel(const float* __restrict__ img,
                 const float* __restrict__ noise,
                 const float* __restrict__ re_mask,
                 const void*  __restrict__ sel,
                 const void*  __restrict__ mix_sel,
                 float* __restrict__ out)
{
    const int b  = blockIdx.z;
    const int y0 = blockIdx.y * TS;
    const int x0 = blockIdx.x * TS;
    const int tid = threadIdx.x;

    const bool apply = read_flag(sel, b);
    if (!apply) {
        // out = img for this tile (whole-batch copy path)
        for (int t = tid; t < 3 * TS * TS; t += 256) {
            int c = t / (TS * TS); int r = t % (TS * TS);
            int ty = r / TS, tx = r % TS;
            size_t g = (((size_t)(b * 3 + c)) * 512 + (y0 + ty)) * 512 + (x0 + tx);
            out[g] = img[g];
        }
        return;
    }
    const bool mix = read_flag(mix_sel, b);

    extern __shared__ float sm[];
    float* smimgp = sm;                                   // [3][PS][IMGP_PITCH]
    float* smw    = smimgp + 3 * PS * IMGP_PITCH;         // [9][R2S][W_PITCH]
    float* smr    = smw    + 9 * R2S * W_PITCH;           // [R2S][R_PITCH]
    float* smmod  = smr    + R2S * R_PITCH;               // [R1S][MOD_PITCH]

    // ---- Phase A: img_p = pad(img)+noise over tile+3 halo ----
    for (int t = tid; t < 3 * PS * PS; t += 256) {
        int c = t / (PS * PS); int r = t % (PS * PS);
        int iy = r / PS, ix = r % PS;
        int gy = y0 - 3 + iy, gx = x0 - 3 + ix;   // unpadded coords; padded = +1
        float v = 0.f;
        if (gy >= -1 && gy <= 512 && gx >= -1 && gx <= 512) {
            v = noise[(((size_t)(b * 3 + c)) * 514 + (gy + 1)) * 514 + (gx + 1)];
            if ((unsigned)gy < 512u && (unsigned)gx < 512u)
                v += img[(((size_t)(b * 3 + c)) * 512 + gy) * 512 + gx];
        }
        smimgp[(c * PS + iy) * IMGP_PITCH + ix] = v;
    }
    __syncthreads();

    // ---- Phase B: stage1 over tile+2 halo ----
    // min_c exp(-t_c) == exp(-max_c t_c): one exp per tap.
    for (int t = tid; t < R2S * R2S; t += 256) {
        int py = t / R2S, px = t % R2S;
        int gy = y0 - 2 + py, gx = x0 - 2 + px;
        float rv = 0.f;  // zero-pad value of img_r for out-of-image positions
        if ((unsigned)gy < 512u && (unsigned)gx < 512u) {
            float sv[9];    // sum over channels of v at tap k
            float tmax[9];  // max over channels of d^2/(2 var)
            #pragma unroll
            for (int c = 0; c < 3; c++) {
                float v9[9];
                float s = 0.f;
                #pragma unroll
                for (int k = 0; k < 9; k++) {
                    float v = smimgp[(c * PS + py + k / 3) * IMGP_PITCH + px + (k % 3)];
                    v9[k] = v; s += v;
                }
                float m = s * (1.f / 9.f);
                float s2 = 0.f;
                #pragma unroll
                for (int k = 0; k < 9; k++) { float d = v9[k] - m; s2 += d * d; }
                float inv = __fdividef(4.f, s2);   // 1/(2*var), var = s2/8 (ddof=1)
                #pragma unroll
                for (int k = 0; k < 9; k++) {
                    float d = v9[k] - m;
                    float tk = (d * d) * inv;
                    if (c == 0) { tmax[k] = tk; sv[k] = v9[k]; }
                    else        { tmax[k] = fmaxf(tmax[k], tk); sv[k] += v9[k]; }
                }
            }
            float den = 0.f, num = 0.f;
            #pragma unroll
            for (int k = 0; k < 9; k++) {
                float w = __expf(-tmax[k]);
                smw[(k * R2S + py) * W_PITCH + px] = w;
                den += w;
                num += sv[k] * w;
            }
            rv = __fdividef(num, den);
        }
        smr[py * R_PITCH + px] = rv;
    }
    __syncthreads();

    // ---- Phase C: stage2 over tile+1 halo ----
    for (int t = tid; t < R1S * R1S; t += 256) {
        int qy = t / R1S, qx = t % R1S;
        int gy = y0 - 1 + qy, gx = x0 - 1 + qx;
        float mv = 0.f;  // zero-pad value of img_3d_mod
        if ((unsigned)gy < 512u && (unsigned)gx < 512u) {
            float bmin =  3.4e38f; int amin = 0;
            float bmax = -3.4e38f; int amax = 0;
            #pragma unroll
            for (int k = 0; k < 9; k++) {
                float v = smr[(qy + k / 3) * R_PITCH + qx + (k % 3)];
                if (v < bmin) { bmin = v; amin = k; }   // first occurrence == jnp.argmin
                if (v > bmax) { bmax = v; amax = k; }   // first occurrence == jnp.argmax
            }
            int id = mix ? amax : amin;
            mv = smw[(id * R2S + (qy + 1)) * W_PITCH + (qx + 1)];
        }
        smmod[qy * MOD_PITCH + qx] = mv;
    }
    __syncthreads();

    // ---- Phase D: stage3 + blend + write ----
    for (int t = tid; t < TS * TS; t += 256) {
        int ty = t / TS, tx = t % TS;
        float m[9]; float den = 0.f;
        #pragma unroll
        for (int k = 0; k < 9; k++) {
            m[k] = smmod[(ty + k / 3) * MOD_PITCH + tx + (k % 3)];
            den += m[k];
        }
        float invden = __fdividef(1.f, den);
        size_t base = (((size_t)(b * 3)) * 512 + (y0 + ty)) * 512 + (x0 + tx);
        #pragma unroll
        for (int c = 0; c < 3; c++) {
            float num = 0.f;
            #pragma unroll
            for (int k = 0; k < 9; k++)
                num += smimgp[(c * PS + ty + 2 + k / 3) * IMGP_PITCH + tx + 2 + (k % 3)] * m[k];
            float imod = num * invden;
            size_t g = base + (size_t)c * 512 * 512;
            float re = re_mask[g];
            float iv = img[g];
            out[g] = imod * (1.f - re) + iv * re;
        }
    }
}

extern "C" void kernel_launch(void* const* d_in, const int* in_sizes, int n_in,
                              void* d_out, int out_size) {
    const float* img     = (const float*)d_in[0];
    const float* noise   = (const float*)d_in[1];
    const float* re_mask = (const float*)d_in[2];
    const void*  sel     = d_in[3];
    const void*  mix_sel = d_in[4];
    float* out = (float*)d_out;

    cudaFuncSetAttribute(gdfn_kernel, cudaFuncAttributeMaxDynamicSharedMemorySize, SMEM_BYTES);
    dim3 grid(512 / TS, 512 / TS, 8);
    gdfn_kernel<<<grid, 256, SMEM_BYTES>>>(img, noise, re_mask, sel, mix_sel, out);
}

// round 3
// speedup vs baseline: 1.4253x; 1.0793x over previous
#include <cuda_runtime.h>

// gdfn_region_batch round 3:
//  - no smw: phase C recomputes the selected weight (1 exp) instead of
//    reading from a 48KB 9-plane weight cache.  SMEM 74KB -> 51KB.
//  - rectangular 64x32 tile (divides 512 exactly), halo 1.27x -> 1.20x,
//    loop-tail waste in heavy phase 15.6% -> 4.4%.
//  - __launch_bounds__(256,4): 4 CTAs/SM, occupancy ~50%.

#define TX 64
#define TY 32
#define PSX 70
#define PSY 38
#define P_PITCH 71
#define R2X 68
#define R2Y 36
#define R2_PITCH 69
#define R1X 66
#define R1Y 34
#define R1_PITCH 67

#define SMEM_FLOATS (3*PSY*P_PITCH + R2Y*R2_PITCH + R1Y*R1_PITCH)
#define SMEM_BYTES  (SMEM_FLOATS * 4)

// sel / mix_sel may arrive as int32 (4B) or bool (1B). For int32 storage the
// pad bytes {1,2,3,5,6,7} are always zero (values are 0/1); for bool storage
// they hold elements 1,2,3,5,6,7. Deterministic per dataset.
__device__ __forceinline__ bool read_flag(const void* p, int b) {
    const unsigned char* u = (const unsigned char*)p;
    unsigned probe = (unsigned)u[1] | u[2] | u[3] | u[5] | u[6] | u[7];
    if (probe == 0u) return ((const int*)p)[b] != 0;   // int32-like
    return u[b] != 0;                                   // bool-like
}

__global__ __launch_bounds__(256, 4)
void gdfn_kernel(const float* __restrict__ img,
                 const float* __restrict__ noise,
                 const float* __restrict__ re_mask,
                 const void*  __restrict__ sel,
                 const void*  __restrict__ mix_sel,
                 float* __restrict__ out)
{
    const int b  = blockIdx.z;
    const int y0 = blockIdx.y * TY;
    const int x0 = blockIdx.x * TX;
    const int tid = threadIdx.x;

    const bool apply = read_flag(sel, b);
    if (!apply) {
        // out = img for this tile, vectorized float4 (rows are 16B aligned)
        const float4* src = (const float4*)img;
        float4* dst = (float4*)out;
        for (int t = tid; t < 3 * TY * (TX / 4); t += 256) {
            int c = t / (TY * (TX / 4)); int r = t % (TY * (TX / 4));
            int ty = r / (TX / 4), tx4 = r % (TX / 4);
            size_t g = ((((size_t)(b * 3 + c)) * 512 + (y0 + ty)) * 512 + x0) / 4 + tx4;
            dst[g] = src[g];
        }
        return;
    }
    const bool mix = read_flag(mix_sel, b);

    extern __shared__ float sm[];
    float* smimgp = sm;                            // [3][PSY][P_PITCH]
    float* smr    = smimgp + 3 * PSY * P_PITCH;    // [R2Y][R2_PITCH]
    float* smmod  = smr    + R2Y * R2_PITCH;       // [R1Y][R1_PITCH]

    // ---- Phase A: img_p = pad(img)+noise over tile+3 halo ----
    for (int t = tid; t < 3 * PSY * PSX; t += 256) {
        int c = t / (PSY * PSX); int r = t % (PSY * PSX);
        int iy = r / PSX, ix = r % PSX;
        int gy = y0 - 3 + iy, gx = x0 - 3 + ix;   // unpadded coords; padded = +1
        float v = 0.f;
        if (gy >= -1 && gy <= 512 && gx >= -1 && gx <= 512) {
            v = noise[(((size_t)(b * 3 + c)) * 514 + (gy + 1)) * 514 + (gx + 1)];
            if ((unsigned)gy < 512u && (unsigned)gx < 512u)
                v += img[(((size_t)(b * 3 + c)) * 512 + gy) * 512 + gx];
        }
        smimgp[(c * PSY + iy) * P_PITCH + ix] = v;
    }
    __syncthreads();

    // ---- Phase B: stage1 (img_r) over tile+2 halo ----
    // min_c exp(-t_c) == exp(-max_c t_c): one exp per tap.
    for (int t = tid; t < R2Y * R2X; t += 256) {
        int py = t / R2X, px = t % R2X;
        int gy = y0 - 2 + py, gx = x0 - 2 + px;
        float rv = 0.f;  // zero-pad value of img_r for out-of-image positions
        if ((unsigned)gy < 512u && (unsigned)gx < 512u) {
            float sv[9];    // sum over channels of v at tap k
            float tmax[9];  // max over channels of d^2/(2 var)
            #pragma unroll
            for (int c = 0; c < 3; c++) {
                const float* base = &smimgp[(c * PSY + py) * P_PITCH + px];
                float v9[9];
                float s = 0.f;
                #pragma unroll
                for (int k = 0; k < 9; k++) {
                    float v = base[(k / 3) * P_PITCH + (k % 3)];
                    v9[k] = v; s += v;
                }
                float m = s * (1.f / 9.f);
                float s2 = 0.f;
                #pragma unroll
                for (int k = 0; k < 9; k++) { float d = v9[k] - m; s2 += d * d; }
                float inv = __fdividef(4.f, s2);   // 1/(2*var), var = s2/8 (ddof=1)
                #pragma unroll
                for (int k = 0; k < 9; k++) {
                    float d = v9[k] - m;
                    float tk = (d * d) * inv;
                    if (c == 0) { tmax[k] = tk; sv[k] = v9[k]; }
                    else        { tmax[k] = fmaxf(tmax[k], tk); sv[k] += v9[k]; }
                }
            }
            float den = 0.f, num = 0.f;
            #pragma unroll
            for (int k = 0; k < 9; k++) {
                float w = __expf(-tmax[k]);
                den += w;
                num += sv[k] * w;
            }
            rv = __fdividef(num, den);
        }
        smr[py * R2_PITCH + px] = rv;
    }
    __syncthreads();

    // ---- Phase C: stage2 (img_3d_mod) over tile+1 halo ----
    // argmin/argmax of img_r over 3x3, then RECOMPUTE the selected weight.
    for (int t = tid; t < R1Y * R1X; t += 256) {
        int qy = t / R1X, qx = t % R1X;
        int gy = y0 - 1 + qy, gx = x0 - 1 + qx;
        float mv = 0.f;  // zero-pad value of img_3d_mod
        if ((unsigned)gy < 512u && (unsigned)gx < 512u) {
            float bmin =  3.4e38f; int amin = 0;
            float bmax = -3.4e38f; int amax = 0;
            #pragma unroll
            for (int k = 0; k < 9; k++) {
                float v = smr[(qy + k / 3) * R2_PITCH + qx + (k % 3)];
                if (v < bmin) { bmin = v; amin = k; }   // first occurrence == jnp.argmin
                if (v > bmax) { bmax = v; amax = k; }   // first occurrence == jnp.argmax
            }
            int id = mix ? amax : amin;
            int ki = id / 3, kj = id - 3 * ki;
            // recompute w[id] at this pixel: window rows qy+1..qy+3 in P coords
            float tmaxv = 0.f;
            #pragma unroll
            for (int c = 0; c < 3; c++) {
                const float* base = &smimgp[(c * PSY + qy + 1) * P_PITCH + qx + 1];
                float v9[9];
                float s = 0.f;
                #pragma unroll
                for (int k = 0; k < 9; k++) {
                    float v = base[(k / 3) * P_PITCH + (k % 3)];
                    v9[k] = v; s += v;
                }
                float m = s * (1.f / 9.f);
                float s2 = 0.f;
                #pragma unroll
                for (int k = 0; k < 9; k++) { float d = v9[k] - m; s2 += d * d; }
                float inv = __fdividef(4.f, s2);
                float vid = base[ki * P_PITCH + kj];   // dynamic tap
                float d = vid - m;
                float tk = (d * d) * inv;
                tmaxv = (c == 0) ? tk : fmaxf(tmaxv, tk);
            }
            mv = __expf(-tmaxv);
        }
        smmod[qy * R1_PITCH + qx] = mv;
    }
    __syncthreads();

    // ---- Phase D: stage3 + blend + write ----
    for (int t = tid; t < TY * TX; t += 256) {
        int ty = t / TX, tx = t % TX;
        float m[9]; float den = 0.f;
        #pragma unroll
        for (int k = 0; k < 9; k++) {
            m[k] = smmod[(ty + k / 3) * R1_PITCH + tx + (k % 3)];
            den += m[k];
        }
        float invden = __fdividef(1.f, den);
        size_t base = (((size_t)(b * 3)) * 512 + (y0 + ty)) * 512 + (x0 + tx);
        #pragma unroll
        for (int c = 0; c < 3; c++) {
            float num = 0.f;
            const float* pb = &smimgp[(c * PSY + ty + 2) * P_PITCH + tx + 2];
            #pragma unroll
            for (int k = 0; k < 9; k++)
                num += pb[(k / 3) * P_PITCH + (k % 3)] * m[k];
            float imod = num * invden;
            size_t g = base + (size_t)c * 512 * 512;
            float re = re_mask[g];
            float iv = img[g];
            out[g] = imod * (1.f - re) + iv * re;
        }
    }
}

extern "C" void kernel_launch(void* const* d_in, const int* in_sizes, int n_in,
                              void* d_out, int out_size) {
    const float* img     = (const float*)d_in[0];
    const float* noise   = (const float*)d_in[1];
    const float* re_mask = (const float*)d_in[2];
    const void*  sel     = d_in[3];
    const void*  mix_sel = d_in[4];
    float* out = (float*)d_out;

    cudaFuncSetAttribute(gdfn_kernel, cudaFuncAttributeMaxDynamicSharedMemorySize, SMEM_BYTES);
    dim3 grid(512 / TX, 512 / TY, 8);
    gdfn_kernel<<<grid, 256, SMEM_BYTES>>>(img, noise, re_mask, sel, mix_sel, out);
}

// round 4
// speedup vs baseline: 1.4514x; 1.0184x over previous
#include <cuda_runtime.h>

// gdfn_region_batch round 4:
//  - variance via sum-of-squares + fma (no d-pass), rsqrt-folded weights
//  - interior-CTA template specialization (no bounds predicates)
//  - uniform mix branch: only argmin or argmax computed
//  - phase D processes 4 px/thread with float4 global traffic
//  - pairwise reduction trees

#define TX 64
#define TY 32
#define PSX 70
#define PSY 38
#define P_PITCH 71
#define R2X 68
#define R2Y 36
#define R2_PITCH 69
#define R1X 66
#define R1Y 34
#define R1_PITCH 67

#define SMEM_FLOATS (3*PSY*P_PITCH + R2Y*R2_PITCH + R1Y*R1_PITCH)
#define SMEM_BYTES  (SMEM_FLOATS * 4)

// sel / mix_sel may arrive as int32 (4B) or bool (1B). For int32 storage the
// pad bytes {1,2,3,5,6,7} are always zero (values are 0/1); for bool storage
// they hold elements 1,2,3,5,6,7. Deterministic per dataset.
__device__ __forceinline__ bool read_flag(const void* p, int b) {
    const unsigned char* u = (const unsigned char*)p;
    unsigned probe = (unsigned)u[1] | u[2] | u[3] | u[5] | u[6] | u[7];
    if (probe == 0u) return ((const int*)p)[b] != 0;   // int32-like
    return u[b] != 0;                                   // bool-like
}

// 3x3 window stats -> rinv = 2/sqrt(s2), mr = mean*rinv.  v9 returned.
__device__ __forceinline__ void win_stats(const float* base, float v9[9],
                                          float& rinv, float& mr) {
    #pragma unroll
    for (int r = 0; r < 3; r++) {
        v9[r*3+0] = base[r*P_PITCH+0];
        v9[r*3+1] = base[r*P_PITCH+1];
        v9[r*3+2] = base[r*P_PITCH+2];
    }
    float s = ((v9[0]+v9[1])+(v9[2]+v9[3])) + ((v9[4]+v9[5])+(v9[6]+v9[7])) + v9[8];
    float q0 = fmaf(v9[0],v9[0], v9[1]*v9[1]);
    float q1 = fmaf(v9[2],v9[2], v9[3]*v9[3]);
    float q2 = fmaf(v9[4],v9[4], v9[5]*v9[5]);
    float q3 = fmaf(v9[6],v9[6], v9[7]*v9[7]);
    float sq = fmaf(v9[8],v9[8], (q0+q1)+(q2+q3));
    float m  = s * (1.f/9.f);
    float s2 = fmaf(-m, s, sq);          // sum (v-m)^2, ddof applied below
    rinv = 2.f * rsqrtf(s2);             // sqrt(4/s2): tk = ((v-m)*rinv)^2 = d^2*4/s2
    mr   = m * rinv;
}

template<bool INTERIOR>
__device__ __forceinline__ void gdfn_tile(
    const float* __restrict__ img, const float* __restrict__ noise,
    const float* __restrict__ re_mask, float* __restrict__ out,
    int b, int y0, int x0, int tid, bool mix, float* sm)
{
    float* smimgp = sm;                            // [3][PSY][P_PITCH]
    float* smr    = smimgp + 3 * PSY * P_PITCH;    // [R2Y][R2_PITCH]
    float* smmod  = smr    + R2Y * R2_PITCH;       // [R1Y][R1_PITCH]

    // ---- Phase A: img_p = pad(img)+noise over tile+3 halo ----
    for (int t = tid; t < 3 * PSY * PSX; t += 256) {
        int c = t / (PSY * PSX); int r = t % (PSY * PSX);
        int iy = r / PSX, ix = r % PSX;
        int gy = y0 - 3 + iy, gx = x0 - 3 + ix;
        float v;
        if (INTERIOR) {
            v = noise[(((size_t)(b * 3 + c)) * 514 + (gy + 1)) * 514 + (gx + 1)]
              + img[(((size_t)(b * 3 + c)) * 512 + gy) * 512 + gx];
        } else {
            v = 0.f;
            if (gy >= -1 && gy <= 512 && gx >= -1 && gx <= 512) {
                v = noise[(((size_t)(b * 3 + c)) * 514 + (gy + 1)) * 514 + (gx + 1)];
                if ((unsigned)gy < 512u && (unsigned)gx < 512u)
                    v += img[(((size_t)(b * 3 + c)) * 512 + gy) * 512 + gx];
            }
        }
        smimgp[(c * PSY + iy) * P_PITCH + ix] = v;
    }
    __syncthreads();

    // ---- Phase B: stage1 (img_r) over tile+2 halo ----
    for (int t = tid; t < R2Y * R2X; t += 256) {
        int py = t / R2X, px = t % R2X;
        bool valid = true;
        if (!INTERIOR) {
            int gy = y0 - 2 + py, gx = x0 - 2 + px;
            valid = ((unsigned)gy < 512u) && ((unsigned)gx < 512u);
        }
        float rv = 0.f;
        if (valid) {
            float sv[9], tmax[9];
            #pragma unroll
            for (int c = 0; c < 3; c++) {
                const float* base = &smimgp[(c * PSY + py) * P_PITCH + px];
                float v9[9], rinv, mr;
                win_stats(base, v9, rinv, mr);
                #pragma unroll
                for (int k = 0; k < 9; k++) {
                    float u  = fmaf(v9[k], rinv, -mr);
                    float tk = u * u;
                    if (c == 0) { tmax[k] = tk; sv[k] = v9[k]; }
                    else        { tmax[k] = fmaxf(tmax[k], tk); sv[k] += v9[k]; }
                }
            }
            float w[9];
            #pragma unroll
            for (int k = 0; k < 9; k++) w[k] = __expf(-tmax[k]);
            float den = ((w[0]+w[1])+(w[2]+w[3])) + ((w[4]+w[5])+(w[6]+w[7])) + w[8];
            float n0 = fmaf(sv[0],w[0], sv[1]*w[1]);
            float n1 = fmaf(sv[2],w[2], sv[3]*w[3]);
            float n2 = fmaf(sv[4],w[4], sv[5]*w[5]);
            float n3 = fmaf(sv[6],w[6], sv[7]*w[7]);
            float num = fmaf(sv[8],w[8], (n0+n1)+(n2+n3));
            rv = __fdividef(num, den);
        }
        smr[py * R2_PITCH + px] = rv;
    }
    __syncthreads();

    // ---- Phase C: stage2 (img_3d_mod) over tile+1 halo ----
    for (int t = tid; t < R1Y * R1X; t += 256) {
        int qy = t / R1X, qx = t % R1X;
        bool valid = true;
        if (!INTERIOR) {
            int gy = y0 - 1 + qy, gx = x0 - 1 + qx;
            valid = ((unsigned)gy < 512u) && ((unsigned)gx < 512u);
        }
        float mv = 0.f;
        if (valid) {
            const float* rb = &smr[qy * R2_PITCH + qx];
            int id = 0;
            if (mix) {          // argmax, first occurrence
                float best = -3.4e38f;
                #pragma unroll
                for (int k = 0; k < 9; k++) {
                    float v = rb[(k/3) * R2_PITCH + (k%3)];
                    if (v > best) { best = v; id = k; }
                }
            } else {            // argmin, first occurrence
                float best = 3.4e38f;
                #pragma unroll
                for (int k = 0; k < 9; k++) {
                    float v = rb[(k/3) * R2_PITCH + (k%3)];
                    if (v < best) { best = v; id = k; }
                }
            }
            int ki = (id >= 6) ? 2 : ((id >= 3) ? 1 : 0);
            int kj = id - 3 * ki;
            int toff = ki * P_PITCH + kj;
            float tm = 0.f;
            #pragma unroll
            for (int c = 0; c < 3; c++) {
                const float* base = &smimgp[(c * PSY + qy + 1) * P_PITCH + qx + 1];
                float v9[9], rinv, mr;
                win_stats(base, v9, rinv, mr);
                float vid = base[toff];              // dynamic tap (LDS)
                float u = fmaf(vid, rinv, -mr);
                float tk = u * u;
                tm = (c == 0) ? tk : fmaxf(tm, tk);
            }
            mv = __expf(-tm);
        }
        smmod[qy * R1_PITCH + qx] = mv;
    }
    __syncthreads();

    // ---- Phase D: stage3 + blend + write, 4 px per thread ----
    for (int t = tid; t < TY * (TX/4); t += 256) {
        int ty = t / (TX/4), tx4 = (t % (TX/4)) * 4;
        // m window: 3 rows x 6 cols of smmod
        float mm[3][6];
        #pragma unroll
        for (int r = 0; r < 3; r++)
            #pragma unroll
            for (int cc = 0; cc < 6; cc++)
                mm[r][cc] = smmod[(ty + r) * R1_PITCH + tx4 + cc];
        float invden[4];
        #pragma unroll
        for (int j = 0; j < 4; j++) {
            float d = 0.f;
            #pragma unroll
            for (int r = 0; r < 3; r++)
                d += (mm[r][j] + mm[r][j+1]) + mm[r][j+2];
            invden[j] = __fdividef(1.f, d);
        }
        size_t rowbase = (((size_t)(b * 3)) * 512 + (y0 + ty)) * 512 + (x0 + tx4);
        #pragma unroll
        for (int c = 0; c < 3; c++) {
            float pv[3][6];
            #pragma unroll
            for (int r = 0; r < 3; r++)
                #pragma unroll
                for (int cc = 0; cc < 6; cc++)
                    pv[r][cc] = smimgp[(c * PSY + ty + 2 + r) * P_PITCH + tx4 + 2 + cc];
            size_t g = rowbase + (size_t)c * 512 * 512;
            float4 re = *(const float4*)&re_mask[g];
            float4 iv = *(const float4*)&img[g];
            float4 o;
            float* op = &o.x; const float* rp = &re.x; const float* ip = &iv.x;
            #pragma unroll
            for (int j = 0; j < 4; j++) {
                float num = 0.f;
                #pragma unroll
                for (int r = 0; r < 3; r++)
                    #pragma unroll
                    for (int cc = 0; cc < 3; cc++)
                        num = fmaf(pv[r][j+cc], mm[r][cc] /*dummy*/, num);
                // NOTE: weight index must be window-relative, fixed below
                op[j] = num;
            }
            // recompute correctly (overwrites dummy): weights mm[r][cc] with
            // window col cc aligned to output j -> mm[r][j+cc]? No:
            // m_e tap (r,cc) for output j uses mod at (ty+r, tx4+j+cc) = mm[r][j+cc]
            #pragma unroll
            for (int j = 0; j < 4; j++) {
                float num = 0.f;
                #pragma unroll
                for (int r = 0; r < 3; r++) {
                    float a0 = pv[r][j+0] * mm[r][j+0];
                    float a1 = fmaf(pv[r][j+1], mm[r][j+1], a0);
                    num += fmaf(pv[r][j+2], mm[r][j+2], a1);
                }
                float imod = num * invden[j];
                op[j] = fmaf(imod, 1.f - rp[j], ip[j] * rp[j]);
            }
            *(float4*)&out[g] = o;
        }
    }
}

__global__ __launch_bounds__(256, 4)
void gdfn_kernel(const float* __restrict__ img,
                 const float* __restrict__ noise,
                 const float* __restrict__ re_mask,
                 const void*  __restrict__ sel,
                 const void*  __restrict__ mix_sel,
                 float* __restrict__ out)
{
    const int b  = blockIdx.z;
    const int y0 = blockIdx.y * TY;
    const int x0 = blockIdx.x * TX;
    const int tid = threadIdx.x;

    if (!read_flag(sel, b)) {
        const float4* src = (const float4*)img;
        float4* dst = (float4*)out;
        for (int t = tid; t < 3 * TY * (TX / 4); t += 256) {
            int c = t / (TY * (TX / 4)); int r = t % (TY * (TX / 4));
            int ty = r / (TX / 4), tx4 = r % (TX / 4);
            size_t g = ((((size_t)(b * 3 + c)) * 512 + (y0 + ty)) * 512 + x0) / 4 + tx4;
            dst[g] = src[g];
        }
        return;
    }
    const bool mix = read_flag(mix_sel, b);

    extern __shared__ float sm[];
    const bool interior = (x0 >= 64) && (x0 <= 384) && (y0 >= 32) && (y0 <= 448);
    if (interior)
        gdfn_tile<true >(img, noise, re_mask, out, b, y0, x0, tid, mix, sm);
    else
        gdfn_tile<false>(img, noise, re_mask, out, b, y0, x0, tid, mix, sm);
}

extern "C" void kernel_launch(void* const* d_in, const int* in_sizes, int n_in,
                              void* d_out, int out_size) {
    const float* img     = (const float*)d_in[0];
    const float* noise   = (const float*)d_in[1];
    const float* re_mask = (const float*)d_in[2];
    const void*  sel     = d_in[3];
    const void*  mix_sel = d_in[4];
    float* out = (float*)d_out;

    cudaFuncSetAttribute(gdfn_kernel, cudaFuncAttributeMaxDynamicSharedMemorySize, SMEM_BYTES);
    dim3 grid(512 / TX, 512 / TY, 8);
    gdfn_kernel<<<grid, 256, SMEM_BYTES>>>(img, noise, re_mask, sel, mix_sel, out);
}

// round 7
// speedup vs baseline: 1.5677x; 1.0801x over previous
#include <cuda_runtime.h>

// gdfn_region_batch round 5 (second resubmit — rounds 5 and 6 both hit GPU
// acquisition timeouts; no measurement of this variant exists yet):
//  - phase B and phase C process 2 horizontal pixels per thread with a shared
//    3x4 patch: shared column sums for stats, shared channel-sum patch.
//    Cuts LDS ~33% and arithmetic ~15% in the two dominant phases, and gives
//    two independent dependency chains per thread (ILP).
//  - phase D: 4 px/thread, float4 global traffic.
//  - RF-capped at 4 CTAs/SM (64 regs): occupancy lever exhausted; this round
//    targets warp-instruction count.

#define TX 64
#define TY 32
#define PSX 70
#define PSY 38
#define P_PITCH 71
#define R2X 68
#define R2Y 36
#define R2_PITCH 69
#define R1X 66
#define R1Y 34
#define R1_PITCH 67

#define SMEM_FLOATS (3*PSY*P_PITCH + R2Y*R2_PITCH + R1Y*R1_PITCH)
#define SMEM_BYTES  (SMEM_FLOATS * 4)

// sel / mix_sel may arrive as int32 (4B) or bool (1B). For int32 storage the
// pad bytes {1,2,3,5,6,7} are always zero (values are 0/1); for bool storage
// they hold elements 1,2,3,5,6,7. Deterministic per dataset.
__device__ __forceinline__ bool read_flag(const void* p, int b) {
    const unsigned char* u = (const unsigned char*)p;
    unsigned probe = (unsigned)u[1] | u[2] | u[3] | u[5] | u[6] | u[7];
    if (probe == 0u) return ((const int*)p)[b] != 0;   // int32-like
    return u[b] != 0;                                   // bool-like
}

// Stats for two adjacent 3x3 windows from a 3x4 patch p[12] (row-major, 4 cols).
// rinv = 2/sqrt(sum (v-m)^2), mr = mean*rinv  (so t = (v*rinv - mr)^2 = 4 d^2/s2).
__device__ __forceinline__ void patch_stats2(const float p[12],
                                             float& rinv0, float& mr0,
                                             float& rinv1, float& mr1) {
    float cs0 = (p[0] + p[4]) + p[8];
    float cs1 = (p[1] + p[5]) + p[9];
    float cs2 = (p[2] + p[6]) + p[10];
    float cs3 = (p[3] + p[7]) + p[11];
    float cq0 = fmaf(p[0], p[0], fmaf(p[4], p[4], p[8]  * p[8]));
    float cq1 = fmaf(p[1], p[1], fmaf(p[5], p[5], p[9]  * p[9]));
    float cq2 = fmaf(p[2], p[2], fmaf(p[6], p[6], p[10] * p[10]));
    float cq3 = fmaf(p[3], p[3], fmaf(p[7], p[7], p[11] * p[11]));
    float s0 = (cs0 + cs1) + cs2, s1 = (cs1 + cs2) + cs3;
    float q0 = (cq0 + cq1) + cq2, q1 = (cq1 + cq2) + cq3;
    float m0 = s0 * (1.f/9.f),   m1 = s1 * (1.f/9.f);
    float v0 = fmaf(-m0, s0, q0), v1 = fmaf(-m1, s1, q1);   // sum (v-m)^2
    rinv0 = 2.f * rsqrtf(v0);  mr0 = m0 * rinv0;
    rinv1 = 2.f * rsqrtf(v1);  mr1 = m1 * rinv1;
}

template<bool INTERIOR>
__device__ __forceinline__ void gdfn_tile(
    const float* __restrict__ img, const float* __restrict__ noise,
    const float* __restrict__ re_mask, float* __restrict__ out,
    int b, int y0, int x0, int tid, bool mix, float* sm)
{
    float* smimgp = sm;                            // [3][PSY][P_PITCH]
    float* smr    = smimgp + 3 * PSY * P_PITCH;    // [R2Y][R2_PITCH]
    float* smmod  = smr    + R2Y * R2_PITCH;       // [R1Y][R1_PITCH]

    // ---- Phase A: img_p = pad(img)+noise over tile+3 halo ----
    for (int t = tid; t < 3 * PSY * PSX; t += 256) {
        int c = t / (PSY * PSX); int r = t % (PSY * PSX);
        int iy = r / PSX, ix = r % PSX;
        int gy = y0 - 3 + iy, gx = x0 - 3 + ix;
        float v;
        if (INTERIOR) {
            v = noise[(((size_t)(b * 3 + c)) * 514 + (gy + 1)) * 514 + (gx + 1)]
              + img[(((size_t)(b * 3 + c)) * 512 + gy) * 512 + gx];
        } else {
            v = 0.f;
            if (gy >= -1 && gy <= 512 && gx >= -1 && gx <= 512) {
                v = noise[(((size_t)(b * 3 + c)) * 514 + (gy + 1)) * 514 + (gx + 1)];
                if ((unsigned)gy < 512u && (unsigned)gx < 512u)
                    v += img[(((size_t)(b * 3 + c)) * 512 + gy) * 512 + gx];
            }
        }
        smimgp[(c * PSY + iy) * P_PITCH + ix] = v;
    }
    __syncthreads();

    // ---- Phase B: stage1 (img_r) over tile+2 halo, 2 px per thread ----
    // min_c exp(-t_c) == exp(-max_c t_c)
    for (int idx = tid; idx < R2Y * (R2X/2); idx += 256) {
        int py = idx / (R2X/2);
        int px = (idx - py * (R2X/2)) * 2;
        float tmax0[9], tmax1[9], sp[12];
        #pragma unroll
        for (int c = 0; c < 3; c++) {
            const float* base = &smimgp[(c * PSY + py) * P_PITCH + px];
            float p[12];
            #pragma unroll
            for (int r = 0; r < 3; r++) {
                p[r*4+0] = base[r*P_PITCH+0];
                p[r*4+1] = base[r*P_PITCH+1];
                p[r*4+2] = base[r*P_PITCH+2];
                p[r*4+3] = base[r*P_PITCH+3];
            }
            float rinv0, mr0, rinv1, mr1;
            patch_stats2(p, rinv0, mr0, rinv1, mr1);
            #pragma unroll
            for (int k = 0; k < 9; k++) {
                int r = k / 3, cc = k % 3;
                float u0 = fmaf(p[r*4+cc],   rinv0, -mr0);
                float u1 = fmaf(p[r*4+cc+1], rinv1, -mr1);
                float t0 = u0 * u0, t1 = u1 * u1;
                if (c == 0) { tmax0[k] = t0; tmax1[k] = t1; }
                else        { tmax0[k] = fmaxf(tmax0[k], t0);
                              tmax1[k] = fmaxf(tmax1[k], t1); }
            }
            #pragma unroll
            for (int j = 0; j < 12; j++) sp[j] = (c == 0) ? p[j] : sp[j] + p[j];
        }
        float den0 = 0.f, num0 = 0.f, den1 = 0.f, num1 = 0.f;
        #pragma unroll
        for (int k = 0; k < 9; k++) {
            int r = k / 3, cc = k % 3;
            float w0 = __expf(-tmax0[k]);
            float w1 = __expf(-tmax1[k]);
            den0 += w0; num0 = fmaf(sp[r*4+cc],   w0, num0);
            den1 += w1; num1 = fmaf(sp[r*4+cc+1], w1, num1);
        }
        float rv0 = __fdividef(num0, den0);
        float rv1 = __fdividef(num1, den1);
        if (!INTERIOR) {
            int gy = y0 - 2 + py, gx = x0 - 2 + px;
            if (!((unsigned)gy < 512u)) { rv0 = 0.f; rv1 = 0.f; }
            else {
                if (!((unsigned)gx       < 512u)) rv0 = 0.f;
                if (!((unsigned)(gx + 1) < 512u)) rv1 = 0.f;
            }
        }
        smr[py * R2_PITCH + px]     = rv0;
        smr[py * R2_PITCH + px + 1] = rv1;
    }
    __syncthreads();

    // ---- Phase C: stage2 (img_3d_mod) over tile+1 halo, 2 px per thread ----
    for (int idx = tid; idx < R1Y * (R1X/2); idx += 256) {
        int qy = idx / (R1X/2);
        int qx = (idx - qy * (R1X/2)) * 2;
        // img_r 3x4 patch -> two argmin/argmax (first occurrence)
        float rp[12];
        {
            const float* rb = &smr[qy * R2_PITCH + qx];
            #pragma unroll
            for (int r = 0; r < 3; r++) {
                rp[r*4+0] = rb[r*R2_PITCH+0];
                rp[r*4+1] = rb[r*R2_PITCH+1];
                rp[r*4+2] = rb[r*R2_PITCH+2];
                rp[r*4+3] = rb[r*R2_PITCH+3];
            }
        }
        int id0 = 0, id1 = 0;
        if (mix) {
            float b0 = -3.4e38f, b1 = -3.4e38f;
            #pragma unroll
            for (int k = 0; k < 9; k++) {
                int r = k / 3, cc = k % 3;
                float v0 = rp[r*4+cc], v1 = rp[r*4+cc+1];
                if (v0 > b0) { b0 = v0; id0 = k; }
                if (v1 > b1) { b1 = v1; id1 = k; }
            }
        } else {
            float b0 = 3.4e38f, b1 = 3.4e38f;
            #pragma unroll
            for (int k = 0; k < 9; k++) {
                int r = k / 3, cc = k % 3;
                float v0 = rp[r*4+cc], v1 = rp[r*4+cc+1];
                if (v0 < b0) { b0 = v0; id0 = k; }
                if (v1 < b1) { b1 = v1; id1 = k; }
            }
        }
        int ki0 = (id0 >= 6) ? 2 : ((id0 >= 3) ? 1 : 0);
        int kj0 = id0 - 3 * ki0;
        int ki1 = (id1 >= 6) ? 2 : ((id1 >= 3) ? 1 : 0);
        int kj1 = id1 - 3 * ki1;
        int toff0 = ki0 * P_PITCH + kj0;
        int toff1 = ki1 * P_PITCH + kj1 + 1;
        float tm0 = 0.f, tm1 = 0.f;
        #pragma unroll
        for (int c = 0; c < 3; c++) {
            const float* base = &smimgp[(c * PSY + qy + 1) * P_PITCH + qx + 1];
            float p[12];
            #pragma unroll
            for (int r = 0; r < 3; r++) {
                p[r*4+0] = base[r*P_PITCH+0];
                p[r*4+1] = base[r*P_PITCH+1];
                p[r*4+2] = base[r*P_PITCH+2];
                p[r*4+3] = base[r*P_PITCH+3];
            }
            float rinv0, mr0, rinv1, mr1;
            patch_stats2(p, rinv0, mr0, rinv1, mr1);
            float v0 = base[toff0];            // dynamic tap (LDS)
            float v1 = base[toff1];
            float u0 = fmaf(v0, rinv0, -mr0);
            float u1 = fmaf(v1, rinv1, -mr1);
            float t0 = u0 * u0, t1 = u1 * u1;
            if (c == 0) { tm0 = t0; tm1 = t1; }
            else        { tm0 = fmaxf(tm0, t0); tm1 = fmaxf(tm1, t1); }
        }
        float mv0 = __expf(-tm0);
        float mv1 = __expf(-tm1);
        if (!INTERIOR) {
            int gy = y0 - 1 + qy, gx = x0 - 1 + qx;
            if (!((unsigned)gy < 512u)) { mv0 = 0.f; mv1 = 0.f; }
            else {
                if (!((unsigned)gx       < 512u)) mv0 = 0.f;
                if (!((unsigned)(gx + 1) < 512u)) mv1 = 0.f;
            }
        }
        smmod[qy * R1_PITCH + qx]     = mv0;
        smmod[qy * R1_PITCH + qx + 1] = mv1;
    }
    __syncthreads();

    // ---- Phase D: stage3 + blend + write, 4 px per thread ----
    for (int t = tid; t < TY * (TX/4); t += 256) {
        int ty = t / (TX/4), tx4 = (t % (TX/4)) * 4;
        float mm[3][6];
        #pragma unroll
        for (int r = 0; r < 3; r++)
            #pragma unroll
            for (int cc = 0; cc < 6; cc++)
                mm[r][cc] = smmod[(ty + r) * R1_PITCH + tx4 + cc];
        float invden[4];
        #pragma unroll
        for (int j = 0; j < 4; j++) {
            float d = 0.f;
            #pragma unroll
            for (int r = 0; r < 3; r++)
                d += (mm[r][j] + mm[r][j+1]) + mm[r][j+2];
            invden[j] = __fdividef(1.f, d);
        }
        size_t rowbase = (((size_t)(b * 3)) * 512 + (y0 + ty)) * 512 + (x0 + tx4);
        #pragma unroll
        for (int c = 0; c < 3; c++) {
            float pv[3][6];
            #pragma unroll
            for (int r = 0; r < 3; r++)
                #pragma unroll
                for (int cc = 0; cc < 6; cc++)
                    pv[r][cc] = smimgp[(c * PSY + ty + 2 + r) * P_PITCH + tx4 + 2 + cc];
            size_t g = rowbase + (size_t)c * 512 * 512;
            float4 re = *(const float4*)&re_mask[g];
            float4 iv = *(const float4*)&img[g];
            float4 o;
            float* op = &o.x; const float* rp2 = &re.x; const float* ip = &iv.x;
            #pragma unroll
            for (int j = 0; j < 4; j++) {
                float num = 0.f;
                #pragma unroll
                for (int r = 0; r < 3; r++) {
                    float a0 = pv[r][j+0] * mm[r][j+0];
                    float a1 = fmaf(pv[r][j+1], mm[r][j+1], a0);
                    num += fmaf(pv[r][j+2], mm[r][j+2], a1);
                }
                float imod = num * invden[j];
                op[j] = fmaf(imod, 1.f - rp2[j], ip[j] * rp2[j]);
            }
            *(float4*)&out[g] = o;
        }
    }
}

__global__ __launch_bounds__(256, 4)
void gdfn_kernel(const float* __restrict__ img,
                 const float* __restrict__ noise,
                 const float* __restrict__ re_mask,
                 const void*  __restrict__ sel,
                 const void*  __restrict__ mix_sel,
                 float* __restrict__ out)
{
    const int b  = blockIdx.z;
    const int y0 = blockIdx.y * TY;
    const int x0 = blockIdx.x * TX;
    const int tid = threadIdx.x;

    if (!read_flag(sel, b)) {
        const float4* src = (const float4*)img;
        float4* dst = (float4*)out;
        for (int t = tid; t < 3 * TY * (TX / 4); t += 256) {
            int c = t / (TY * (TX / 4)); int r = t % (TY * (TX / 4));
            int ty = r / (TX / 4), tx4 = r % (TX / 4);
            size_t g = ((((size_t)(b * 3 + c)) * 512 + (y0 + ty)) * 512 + x0) / 4 + tx4;
            dst[g] = src[g];
        }
        return;
    }
    const bool mix = read_flag(mix_sel, b);

    extern __shared__ float sm[];
    const bool interior = (x0 >= 64) && (x0 <= 384) && (y0 >= 32) && (y0 <= 448);
    if (interior)
        gdfn_tile<true >(img, noise, re_mask, out, b, y0, x0, tid, mix, sm);
    else
        gdfn_tile<false>(img, noise, re_mask, out, b, y0, x0, tid, mix, sm);
}

extern "C" void kernel_launch(void* const* d_in, const int* in_sizes, int n_in,
                              void* d_out, int out_size) {
    const float* img     = (const float*)d_in[0];
    const float* noise   = (const float*)d_in[1];
    const float* re_mask = (const float*)d_in[2];
    const void*  sel     = d_in[3];
    const void*  mix_sel = d_in[4];
    float* out = (float*)d_out;

    cudaFuncSetAttribute(gdfn_kernel, cudaFuncAttributeMaxDynamicSharedMemorySize, SMEM_BYTES);
    dim3 grid(512 / TX, 512 / TY, 8);
    gdfn_kernel<<<grid, 256, SMEM_BYTES>>>(img, noise, re_mask, sel, mix_sel, out);
}

// round 17
// speedup vs baseline: 1.6265x; 1.0375x over previous
#include <cuda_runtime.h>

// gdfn_region_batch round 8 (tenth resubmit — broker timeouts rounds 8-16;
// variant still unmeasured vs the 45.2us round-7 best):
//  - ALL shared-memory patch traffic vectorized to float2 (LDS.64/STS.64):
//    pitches made even (P 72, R2 70, R1 68); phase B/C pixel pairs start at
//    even columns, phase D at multiples of 4, so every patch row is 2-3
//    aligned float2 loads instead of 4-6 scalar loads.
//  - arithmetic order is bit-identical to round 7 (argmin flips unchanged).
//  - SMEM 50.9KB/CTA -> still 4 CTAs/SM.

#define TX 64
#define TY 32
#define PSX 70
#define PSY 38
#define P_PITCH 72
#define R2X 68
#define R2Y 36
#define R2_PITCH 70
#define R1X 66
#define R1Y 34
#define R1_PITCH 68

#define SMEM_FLOATS (3*PSY*P_PITCH + R2Y*R2_PITCH + R1Y*R1_PITCH)
#define SMEM_BYTES  (SMEM_FLOATS * 4)

// sel / mix_sel may arrive as int32 (4B) or bool (1B). For int32 storage the
// pad bytes {1,2,3,5,6,7} are always zero (values are 0/1); for bool storage
// they hold elements 1,2,3,5,6,7. Deterministic per dataset.
__device__ __forceinline__ bool read_flag(const void* p, int b) {
    const unsigned char* u = (const unsigned char*)p;
    unsigned probe = (unsigned)u[1] | u[2] | u[3] | u[5] | u[6] | u[7];
    if (probe == 0u) return ((const int*)p)[b] != 0;   // int32-like
    return u[b] != 0;                                   // bool-like
}

// Stats for two adjacent 3x3 windows from a 3x4 patch p[12] (row-major, 4 cols).
// rinv = 2/sqrt(sum (v-m)^2), mr = mean*rinv  (so t = (v*rinv - mr)^2 = 4 d^2/s2).
__device__ __forceinline__ void patch_stats2(const float p[12],
                                             float& rinv0, float& mr0,
                                             float& rinv1, float& mr1) {
    float cs0 = (p[0] + p[4]) + p[8];
    float cs1 = (p[1] + p[5]) + p[9];
    float cs2 = (p[2] + p[6]) + p[10];
    float cs3 = (p[3] + p[7]) + p[11];
    float cq0 = fmaf(p[0], p[0], fmaf(p[4], p[4], p[8]  * p[8]));
    float cq1 = fmaf(p[1], p[1], fmaf(p[5], p[5], p[9]  * p[9]));
    float cq2 = fmaf(p[2], p[2], fmaf(p[6], p[6], p[10] * p[10]));
    float cq3 = fmaf(p[3], p[3], fmaf(p[7], p[7], p[11] * p[11]));
    float s0 = (cs0 + cs1) + cs2, s1 = (cs1 + cs2) + cs3;
    float q0 = (cq0 + cq1) + cq2, q1 = (cq1 + cq2) + cq3;
    float m0 = s0 * (1.f/9.f),   m1 = s1 * (1.f/9.f);
    float v0 = fmaf(-m0, s0, q0), v1 = fmaf(-m1, s1, q1);   // sum (v-m)^2
    rinv0 = 2.f * rsqrtf(v0);  mr0 = m0 * rinv0;
    rinv1 = 2.f * rsqrtf(v1);  mr1 = m1 * rinv1;
}

template<bool INTERIOR>
__device__ __forceinline__ void gdfn_tile(
    const float* __restrict__ img, const float* __restrict__ noise,
    const float* __restrict__ re_mask, float* __restrict__ out,
    int b, int y0, int x0, int tid, bool mix, float* sm)
{
    float* smimgp = sm;                            // [3][PSY][P_PITCH]
    float* smr    = smimgp + 3 * PSY * P_PITCH;    // [R2Y][R2_PITCH]  (even offset)
    float* smmod  = smr    + R2Y * R2_PITCH;       // [R1Y][R1_PITCH]  (even offset)

    // ---- Phase A: img_p = pad(img)+noise over tile+3 halo ----
    for (int t = tid; t < 3 * PSY * PSX; t += 256) {
        int c = t / (PSY * PSX); int r = t % (PSY * PSX);
        int iy = r / PSX, ix = r % PSX;
        int gy = y0 - 3 + iy, gx = x0 - 3 + ix;
        float v;
        if (INTERIOR) {
            v = noise[(((size_t)(b * 3 + c)) * 514 + (gy + 1)) * 514 + (gx + 1)]
              + img[(((size_t)(b * 3 + c)) * 512 + gy) * 512 + gx];
        } else {
            v = 0.f;
            if (gy >= -1 && gy <= 512 && gx >= -1 && gx <= 512) {
                v = noise[(((size_t)(b * 3 + c)) * 514 + (gy + 1)) * 514 + (gx + 1)];
                if ((unsigned)gy < 512u && (unsigned)gx < 512u)
                    v += img[(((size_t)(b * 3 + c)) * 512 + gy) * 512 + gx];
            }
        }
        smimgp[(c * PSY + iy) * P_PITCH + ix] = v;
    }
    __syncthreads();

    // ---- Phase B: stage1 (img_r) over tile+2 halo, 2 px per thread ----
    // min_c exp(-t_c) == exp(-max_c t_c)
    for (int idx = tid; idx < R2Y * (R2X/2); idx += 256) {
        int py = idx / (R2X/2);
        int px = (idx - py * (R2X/2)) * 2;          // even
        float tmax0[9], tmax1[9], sp[12];
        #pragma unroll
        for (int c = 0; c < 3; c++) {
            const float* base = &smimgp[(c * PSY + py) * P_PITCH + px]; // 8B aligned
            float p[12];
            #pragma unroll
            for (int r = 0; r < 3; r++) {
                float2 a = *(const float2*)(base + r * P_PITCH);       // cols 0,1
                float2 d = *(const float2*)(base + r * P_PITCH + 2);   // cols 2,3
                p[r*4+0] = a.x; p[r*4+1] = a.y; p[r*4+2] = d.x; p[r*4+3] = d.y;
            }
            float rinv0, mr0, rinv1, mr1;
            patch_stats2(p, rinv0, mr0, rinv1, mr1);
            #pragma unroll
            for (int k = 0; k < 9; k++) {
                int r = k / 3, cc = k % 3;
                float u0 = fmaf(p[r*4+cc],   rinv0, -mr0);
                float u1 = fmaf(p[r*4+cc+1], rinv1, -mr1);
                float t0 = u0 * u0, t1 = u1 * u1;
                if (c == 0) { tmax0[k] = t0; tmax1[k] = t1; }
                else        { tmax0[k] = fmaxf(tmax0[k], t0);
                              tmax1[k] = fmaxf(tmax1[k], t1); }
            }
            #pragma unroll
            for (int j = 0; j < 12; j++) sp[j] = (c == 0) ? p[j] : sp[j] + p[j];
        }
        float den0 = 0.f, num0 = 0.f, den1 = 0.f, num1 = 0.f;
        #pragma unroll
        for (int k = 0; k < 9; k++) {
            int r = k / 3, cc = k % 3;
            float w0 = __expf(-tmax0[k]);
            float w1 = __expf(-tmax1[k]);
            den0 += w0; num0 = fmaf(sp[r*4+cc],   w0, num0);
            den1 += w1; num1 = fmaf(sp[r*4+cc+1], w1, num1);
        }
        float rv0 = __fdividef(num0, den0);
        float rv1 = __fdividef(num1, den1);
        if (!INTERIOR) {
            int gy = y0 - 2 + py, gx = x0 - 2 + px;
            if (!((unsigned)gy < 512u)) { rv0 = 0.f; rv1 = 0.f; }
            else {
                if (!((unsigned)gx       < 512u)) rv0 = 0.f;
                if (!((unsigned)(gx + 1) < 512u)) rv1 = 0.f;
            }
        }
        *(float2*)&smr[py * R2_PITCH + px] = make_float2(rv0, rv1);   // STS.64
    }
    __syncthreads();

    // ---- Phase C: stage2 (img_3d_mod) over tile+1 halo, 2 px per thread ----
    for (int idx = tid; idx < R1Y * (R1X/2); idx += 256) {
        int qy = idx / (R1X/2);
        int qx = (idx - qy * (R1X/2)) * 2;          // even
        // img_r 3x4 patch -> two argmin/argmax (first occurrence)
        float rp[12];
        {
            const float* rb = &smr[qy * R2_PITCH + qx];                // 8B aligned
            #pragma unroll
            for (int r = 0; r < 3; r++) {
                float2 a = *(const float2*)(rb + r * R2_PITCH);
                float2 d = *(const float2*)(rb + r * R2_PITCH + 2);
                rp[r*4+0] = a.x; rp[r*4+1] = a.y; rp[r*4+2] = d.x; rp[r*4+3] = d.y;
            }
        }
        int id0 = 0, id1 = 0;
        if (mix) {
            float b0 = -3.4e38f, b1 = -3.4e38f;
            #pragma unroll
            for (int k = 0; k < 9; k++) {
                int r = k / 3, cc = k % 3;
                float v0 = rp[r*4+cc], v1 = rp[r*4+cc+1];
                if (v0 > b0) { b0 = v0; id0 = k; }
                if (v1 > b1) { b1 = v1; id1 = k; }
            }
        } else {
            float b0 = 3.4e38f, b1 = 3.4e38f;
            #pragma unroll
            for (int k = 0; k < 9; k++) {
                int r = k / 3, cc = k % 3;
                float v0 = rp[r*4+cc], v1 = rp[r*4+cc+1];
                if (v0 < b0) { b0 = v0; id0 = k; }
                if (v1 < b1) { b1 = v1; id1 = k; }
            }
        }
        int ki0 = (id0 >= 6) ? 2 : ((id0 >= 3) ? 1 : 0);
        int kj0 = id0 - 3 * ki0;
        int ki1 = (id1 >= 6) ? 2 : ((id1 >= 3) ? 1 : 0);
        int kj1 = id1 - 3 * ki1;
        float tm0 = 0.f, tm1 = 0.f;
        #pragma unroll
        for (int c = 0; c < 3; c++) {
            // window patch is cols qx+1..qx+4; load aligned pairs covering qx..qx+5
            const float* balign = &smimgp[(c * PSY + qy + 1) * P_PITCH + qx]; // 8B aligned
            float p[12];
            #pragma unroll
            for (int r = 0; r < 3; r++) {
                float2 a = *(const float2*)(balign + r * P_PITCH);       // cols 0,1
                float2 d = *(const float2*)(balign + r * P_PITCH + 2);   // cols 2,3
                float2 e = *(const float2*)(balign + r * P_PITCH + 4);   // cols 4,5
                p[r*4+0] = a.y; p[r*4+1] = d.x; p[r*4+2] = d.y; p[r*4+3] = e.x;
            }
            float rinv0, mr0, rinv1, mr1;
            patch_stats2(p, rinv0, mr0, rinv1, mr1);
            float v0 = balign[ki0 * P_PITCH + kj0 + 1];   // dynamic tap (LDS)
            float v1 = balign[ki1 * P_PITCH + kj1 + 2];
            float u0 = fmaf(v0, rinv0, -mr0);
            float u1 = fmaf(v1, rinv1, -mr1);
            float t0 = u0 * u0, t1 = u1 * u1;
            if (c == 0) { tm0 = t0; tm1 = t1; }
            else        { tm0 = fmaxf(tm0, t0); tm1 = fmaxf(tm1, t1); }
        }
        float mv0 = __expf(-tm0);
        float mv1 = __expf(-tm1);
        if (!INTERIOR) {
            int gy = y0 - 1 + qy, gx = x0 - 1 + qx;
            if (!((unsigned)gy < 512u)) { mv0 = 0.f; mv1 = 0.f; }
            else {
                if (!((unsigned)gx       < 512u)) mv0 = 0.f;
                if (!((unsigned)(gx + 1) < 512u)) mv1 = 0.f;
            }
        }
        *(float2*)&smmod[qy * R1_PITCH + qx] = make_float2(mv0, mv1);  // STS.64
    }
    __syncthreads();

    // ---- Phase D: stage3 + blend + write, 4 px per thread ----
    for (int t = tid; t < TY * (TX/4); t += 256) {
        int ty = t / (TX/4), tx4 = (t % (TX/4)) * 4;   // multiple of 4 -> even
        float mm[3][6];
        #pragma unroll
        for (int r = 0; r < 3; r++) {
            const float* mp = &smmod[(ty + r) * R1_PITCH + tx4];       // 8B aligned
            float2 a = *(const float2*)(mp + 0);
            float2 d = *(const float2*)(mp + 2);
            float2 e = *(const float2*)(mp + 4);
            mm[r][0] = a.x; mm[r][1] = a.y; mm[r][2] = d.x;
            mm[r][3] = d.y; mm[r][4] = e.x; mm[r][5] = e.y;
        }
        float invden[4];
        #pragma unroll
        for (int j = 0; j < 4; j++) {
            float d = 0.f;
            #pragma unroll
            for (int r = 0; r < 3; r++)
                d += (mm[r][j] + mm[r][j+1]) + mm[r][j+2];
            invden[j] = __fdividef(1.f, d);
        }
        size_t rowbase = (((size_t)(b * 3)) * 512 + (y0 + ty)) * 512 + (x0 + tx4);
        #pragma unroll
        for (int c = 0; c < 3; c++) {
            float pv[3][6];
            #pragma unroll
            for (int r = 0; r < 3; r++) {
                const float* pp = &smimgp[(c * PSY + ty + 2 + r) * P_PITCH + tx4 + 2]; // even -> aligned
                float2 a = *(const float2*)(pp + 0);
                float2 d = *(const float2*)(pp + 2);
                float2 e = *(const float2*)(pp + 4);
                pv[r][0] = a.x; pv[r][1] = a.y; pv[r][2] = d.x;
                pv[r][3] = d.y; pv[r][4] = e.x; pv[r][5] = e.y;
            }
            size_t g = rowbase + (size_t)c * 512 * 512;
            float4 re = *(const float4*)&re_mask[g];
            float4 iv = *(const float4*)&img[g];
            float4 o;
            float* op = &o.x; const float* rp2 = &re.x; const float* ip = &iv.x;
            #pragma unroll
            for (int j = 0; j < 4; j++) {
                float num = 0.f;
                #pragma unroll
                for (int r = 0; r < 3; r++) {
                    float a0 = pv[r][j+0] * mm[r][j+0];
                    float a1 = fmaf(pv[r][j+1], mm[r][j+1], a0);
                    num += fmaf(pv[r][j+2], mm[r][j+2], a1);
                }
                float imod = num * invden[j];
                op[j] = fmaf(imod, 1.f - rp2[j], ip[j] * rp2[j]);
            }
            *(float4*)&out[g] = o;
        }
    }
}

__global__ __launch_bounds__(256, 4)
void gdfn_kernel(const float* __restrict__ img,
                 const float* __restrict__ noise,
                 const float* __restrict__ re_mask,
                 const void*  __restrict__ sel,
                 const void*  __restrict__ mix_sel,
                 float* __restrict__ out)
{
    const int b  = blockIdx.z;
    const int y0 = blockIdx.y * TY;
    const int x0 = blockIdx.x * TX;
    const int tid = threadIdx.x;

    if (!read_flag(sel, b)) {
        const float4* src = (const float4*)img;
        float4* dst = (float4*)out;
        for (int t = tid; t < 3 * TY * (TX / 4); t += 256) {
            int c = t / (TY * (TX / 4)); int r = t % (TY * (TX / 4));
            int ty = r / (TX / 4), tx4 = r % (TX / 4);
            size_t g = ((((size_t)(b * 3 + c)) * 512 + (y0 + ty)) * 512 + x0) / 4 + tx4;
            dst[g] = src[g];
        }
        return;
    }
    const bool mix = read_flag(mix_sel, b);

    extern __shared__ float sm[];
    const bool interior = (x0 >= 64) && (x0 <= 384) && (y0 >= 32) && (y0 <= 448);
    if (interior)
        gdfn_tile<true >(img, noise, re_mask, out, b, y0, x0, tid, mix, sm);
    else
        gdfn_tile<false>(img, noise, re_mask, out, b, y0, x0, tid, mix, sm);
}

extern "C" void kernel_launch(void* const* d_in, const int* in_sizes, int n_in,
                              void* d_out, int out_size) {
    const float* img     = (const float*)d_in[0];
    const float* noise   = (const float*)d_in[1];
    const float* re_mask = (const float*)d_in[2];
    const void*  sel     = d_in[3];
    const void*  mix_sel = d_in[4];
    float* out = (float*)d_out;

    cudaFuncSetAttribute(gdfn_kernel, cudaFuncAttributeMaxDynamicSharedMemorySize, SMEM_BYTES);
    dim3 grid(512 / TX, 512 / TY, 8);
    gdfn_kernel<<<grid, 256, SMEM_BYTES>>>(img, noise, re_mask, sel, mix_sel, out);
}